// round 6
// baseline (speedup 1.0000x reference)
#include <cuda_runtime.h>
#include <cuda_bf16.h>
#include <cstdint>
#include <math.h>

#define NVOX   500000
#define CCH    64
#define KTAPS  27
#define SBLK   512
#define NBLK   592     // scatter blocks: 2 waves at occ 2 on 148 SMs

// ---------------- static device scratch (no allocs allowed) -----------------
__device__ float g_buf1[(size_t)NVOX * CCH];      // conv out fp32 (pre-BN)
__device__ uint4 g_xhi[(size_t)NVOX * 8];         // bf16 hi features [n][64]
__device__ uint4 g_xlo[(size_t)NVOX * 8];         // bf16 lo features [n][64]
__device__ uint4 g_wt1[KTAPS * 1024];             // W1^T bf16 hi/lo, swizzled
__device__ uint4 g_wt2[KTAPS * 1024];             // W2^T bf16 hi/lo, swizzled
__device__ float g_part[SBLK * 128];
__device__ float g_stats[128];
__device__ int2  g_pairs[(size_t)NVOX * KTAPS];   // compacted (out,in), padded/128
__device__ int   g_bcnt[26 * 64];
__device__ int   g_boff[26 * 64];
__device__ int   g_meta[128];   // [0..26]=tile-base prefix (tb[26]=ntiles), [64+kk]=cnt

// ---------------- helpers ----------------------------------------------------
__device__ __forceinline__ uint32_t smem_u32(const void* p) {
    uint32_t a;
    asm("{ .reg .u64 t; cvta.to.shared.u64 t, %1; cvt.u32.u64 %0, t; }" : "=r"(a) : "l"(p));
    return a;
}
__device__ __host__ __forceinline__ uint32_t sw128(uint32_t off) {
    return off ^ ((off >> 3) & 0x70);
}
__device__ __forceinline__ void ldm_x4(uint32_t* r, uint32_t addr) {
    asm volatile("ldmatrix.sync.aligned.m8n8.x4.shared.b16 {%0,%1,%2,%3}, [%4];"
                 : "=r"(r[0]), "=r"(r[1]), "=r"(r[2]), "=r"(r[3]) : "r"(addr));
}
__device__ __forceinline__ void mma_bf16(float* d, const uint32_t* a,
                                         uint32_t b0, uint32_t b1) {
    asm volatile("mma.sync.aligned.m16n8k16.row.col.f32.bf16.bf16.f32 "
                 "{%0,%1,%2,%3}, {%4,%5,%6,%7}, {%8,%9}, {%0,%1,%2,%3};"
                 : "+f"(d[0]), "+f"(d[1]), "+f"(d[2]), "+f"(d[3])
                 : "r"(a[0]), "r"(a[1]), "r"(a[2]), "r"(a[3]), "r"(b0), "r"(b1));
}
__device__ __forceinline__ void cpa16(uint32_t dst, const void* src, uint32_t sz) {
    asm volatile("cp.async.cg.shared.global [%0], [%1], 16, %2;"
                 :: "r"(dst), "l"(src), "r"(sz) : "memory");
}
#define CP_COMMIT() asm volatile("cp.async.commit_group;" ::: "memory")
#define CP_WAIT0()  asm volatile("cp.async.wait_group 0;" ::: "memory")
__device__ __forceinline__ void redadd(float* p, float v) {
    asm volatile("red.global.add.f32 [%0], %1;" :: "l"(p), "f"(v) : "memory");
}

// shared 3-pass MMA over one 128x64x64 tile (A hi/lo, W hi/lo in smem)
__device__ __forceinline__ void tile_mma(
    uint32_t ab, uint32_t lb, uint32_t wh, uint32_t wl,
    const uint32_t aoff[4][2], const uint32_t boff[4][2], float acc[2][4][4])
{
    #pragma unroll
    for (int kc = 0; kc < 4; ++kc) {
        uint32_t ah[2][4], al[2][4], bh[2][4], bl[2][4];
        #pragma unroll
        for (int mi = 0; mi < 2; ++mi) {
            ldm_x4(ah[mi], ab + aoff[kc][mi]);
            ldm_x4(al[mi], lb + aoff[kc][mi]);
        }
        #pragma unroll
        for (int ni = 0; ni < 2; ++ni) {
            ldm_x4(bh[ni], wh + boff[kc][ni]);
            ldm_x4(bl[ni], wl + boff[kc][ni]);
        }
        #pragma unroll
        for (int mi = 0; mi < 2; ++mi)
            #pragma unroll
            for (int nt = 0; nt < 4; ++nt) {
                int ni = nt >> 1, s = nt & 1;
                mma_bf16(acc[mi][nt], ah[mi], bh[ni][s], bh[ni][s + 2]);
                mma_bf16(acc[mi][nt], ah[mi], bl[ni][s], bl[ni][s + 2]);
                mma_bf16(acc[mi][nt], al[mi], bh[ni][s], bh[ni][s + 2]);
            }
    }
}

// ---------------- compaction: count -> scan -> fill -> pad --------------------
__global__ __launch_bounds__(256) void count_kernel(const float* __restrict__ valid, int n)
{
    const int kk = blockIdx.x >> 6, b = blockIdx.x & 63;
    const int k = kk + (kk >= 13 ? 1 : 0);
    const int chunk = (n + 63) >> 6;
    const int r0 = b * chunk, r1 = min(r0 + chunk, n);
    const int tid = threadIdx.x, lane = tid & 31, wid = tid >> 5;
    int c = 0;
    for (int i = r0 + tid; i < r1; i += 256)
        c += (valid[(size_t)k * n + i] != 0.f);
    #pragma unroll
    for (int d = 16; d > 0; d >>= 1) c += __shfl_down_sync(0xffffffffu, c, d);
    __shared__ int ws[8];
    if (lane == 0) ws[wid] = c;
    __syncthreads();
    if (tid == 0) {
        int t = 0;
        for (int w = 0; w < 8; ++w) t += ws[w];
        g_bcnt[blockIdx.x] = t;
    }
}

__global__ __launch_bounds__(1024) void scan_kernel()
{
    __shared__ int sc[26];
    __shared__ int stb[27];
    const int tid = threadIdx.x, wid = tid >> 5, lane = tid & 31;
    int e0 = 0, e1 = 0;
    if (wid < 26) {
        int v0 = g_bcnt[wid * 64 + lane];
        int v1 = g_bcnt[wid * 64 + 32 + lane];
        int p0 = v0;
        #pragma unroll
        for (int d = 1; d < 32; d <<= 1) {
            int t = __shfl_up_sync(0xffffffffu, p0, d);
            if (lane >= d) p0 += t;
        }
        int tot0 = __shfl_sync(0xffffffffu, p0, 31);
        int p1 = v1;
        #pragma unroll
        for (int d = 1; d < 32; d <<= 1) {
            int t = __shfl_up_sync(0xffffffffu, p1, d);
            if (lane >= d) p1 += t;
        }
        p1 += tot0;
        e0 = p0 - v0;
        e1 = p1 - v1;
        if (lane == 31) sc[wid] = p1;
    }
    __syncthreads();
    if (tid == 0) {
        int tb = 0;
        for (int kk = 0; kk < 26; ++kk) {
            stb[kk] = tb;
            tb += (sc[kk] + 127) >> 7;
            g_meta[64 + kk] = sc[kk];
        }
        stb[26] = tb;
        for (int kk = 0; kk <= 26; ++kk) g_meta[kk] = stb[kk];
    }
    __syncthreads();
    if (wid < 26) {
        int base = stb[wid] * 128;
        g_boff[wid * 64 + lane]      = base + e0;
        g_boff[wid * 64 + 32 + lane] = base + e1;
    }
}

__global__ __launch_bounds__(256) void fill_kernel(
    const int* __restrict__ nbr, const float* __restrict__ valid, int n)
{
    const int kk = blockIdx.x >> 6, b = blockIdx.x & 63;
    const int k = kk + (kk >= 13 ? 1 : 0);
    const int chunk = (n + 63) >> 6;
    const int r0 = b * chunk, r1 = min(r0 + chunk, n);
    const int tid = threadIdx.x, lane = tid & 31, wid = tid >> 5;
    const int base = g_boff[blockIdx.x];
    __shared__ int wb[9];
    int run = 0;
    for (int s = r0; s < r1; s += 256) {
        int i = s + tid;
        bool v = (i < r1) && (valid[(size_t)k * n + i] != 0.f);
        unsigned bal = __ballot_sync(0xffffffffu, v);
        if (lane == 0) wb[wid] = __popc(bal);
        __syncthreads();
        if (tid == 0) {
            int t = 0;
            for (int w = 0; w < 8; ++w) { int x = wb[w]; wb[w] = t; t += x; }
            wb[8] = t;
        }
        __syncthreads();
        if (v) {
            int off = base + run + wb[wid] + __popc(bal & ((1u << lane) - 1u));
            g_pairs[off] = make_int2(i, nbr[(size_t)k * n + i]);
        }
        run += wb[8];
        __syncthreads();
    }
}

__global__ __launch_bounds__(128) void pad_kernel()
{
    const int kk = blockIdx.x;
    const int cnt = g_meta[64 + kk];
    const int base = g_meta[kk] * 128;
    const int padded = (g_meta[kk + 1] - g_meta[kk]) * 128;
    for (int s = cnt + threadIdx.x; s < padded; s += 128)
        g_pairs[base + s] = make_int2(0, -1);
}

// ---------------- center tap: dense GEMM, plain writes ------------------------
#define CEN_SMEM 49152
__global__ __launch_bounds__(256, 2) void center_kernel(
    const uint4* __restrict__ xhi, const uint4* __restrict__ xlo,
    const uint4* __restrict__ wtap, float* __restrict__ out, int n)
{
    extern __shared__ char smem[];
    const uint32_t sb = smem_u32(smem);
    const int tid = threadIdx.x, lane = tid & 31, wid = tid >> 5;
    const int n0 = blockIdx.x * 128;
    const int m0 = (wid & 3) * 32, nb0 = (wid >> 2) * 32;
    const int frow = tid >> 1, fhalf = tid & 1;

    const int g = n0 + frow;
    const uint32_t sz = (g < n) ? 16u : 0u;
    const int gc = min(g, n - 1);
    const char* sh = (const char*)(xhi + (size_t)gc * 8);
    const char* sl = (const char*)(xlo + (size_t)gc * 8);
    #pragma unroll
    for (int j = 0; j < 4; ++j) {
        int c = fhalf * 4 + j;
        uint32_t so = sw128((uint32_t)(frow * 128 + c * 16));
        cpa16(sb + so, sh + c * 16, sz);
        cpa16(sb + 16384 + so, sl + c * 16, sz);
    }
    const char* ws = (const char*)wtap;
    #pragma unroll
    for (int j = 0; j < 2; ++j) {
        int c = tid + j * 256;
        cpa16(sb + 32768 + c * 16, ws + c * 16, 16);
        cpa16(sb + 40960 + c * 16, ws + 8192 + c * 16, 16);
    }
    CP_COMMIT(); CP_WAIT0();
    __syncthreads();

    const uint32_t arow = lane & 15, agrp = (lane >> 4) * 16;
    uint32_t aoff[4][2], boff[4][2];
    #pragma unroll
    for (int kc = 0; kc < 4; ++kc) {
        #pragma unroll
        for (int mi = 0; mi < 2; ++mi)
            aoff[kc][mi] = sw128((uint32_t)((m0 + mi * 16 + arow) * 128 + kc * 32) + agrp);
        #pragma unroll
        for (int ni = 0; ni < 2; ++ni)
            boff[kc][ni] = sw128((uint32_t)((nb0 + ni * 16 + arow) * 128 + kc * 32) + agrp);
    }

    float acc[2][4][4];
    #pragma unroll
    for (int i = 0; i < 2; ++i)
        #pragma unroll
        for (int j = 0; j < 4; ++j)
            #pragma unroll
            for (int q = 0; q < 4; ++q) acc[i][j][q] = 0.f;

    tile_mma(sb, sb + 16384, sb + 32768, sb + 40960, aoff, boff, acc);

    const int rq = lane >> 2, cq = (lane & 3) * 2;
    #pragma unroll
    for (int mi = 0; mi < 2; ++mi)
        #pragma unroll
        for (int nt = 0; nt < 4; ++nt) {
            int col = nb0 + nt * 8 + cq;
            int r0 = n0 + m0 + mi * 16 + rq;
            if (r0 < n)
                *(float2*)(out + (size_t)r0 * CCH + col) = make_float2(acc[mi][nt][0], acc[mi][nt][1]);
            int r1 = r0 + 8;
            if (r1 < n)
                *(float2*)(out + (size_t)r1 * CCH + col) = make_float2(acc[mi][nt][2], acc[mi][nt][3]);
        }
}

// ---------------- scatter conv: contiguous tile chunks, W reuse ---------------
#define SCA(s)     ((s) * 32768)            // A stage: hi 16KB + lo 16KB
#define SCW        65536                    // single W: hi 8KB + lo 8KB
#define SCP(ps)    (81920 + (ps) * 1024)    // pairs, 3 stages
#define SC_TB      84992                    // tile-base table (27 ints)
#define SC_SMEM    85120

__global__ __launch_bounds__(256, 2) void scatter_kernel(
    const uint4* __restrict__ xhi, const uint4* __restrict__ xlo,
    const uint4* __restrict__ wt, float* __restrict__ out)
{
    extern __shared__ char smem[];
    const uint32_t sb = smem_u32(smem);
    const int tid = threadIdx.x, lane = tid & 31, wid = tid >> 5;
    const int m0 = (wid & 3) * 32, nb0 = (wid >> 2) * 32;
    const int frow = tid >> 1, fhalf = tid & 1;

    int* stb = (int*)(smem + SC_TB);
    if (tid < 27) stb[tid] = g_meta[tid];
    __syncthreads();
    const int ntiles = stb[26];
    const int chunk = (ntiles + NBLK - 1) / NBLK;
    const int t0 = blockIdx.x * chunk;
    const int tend = min(t0 + chunk, ntiles);
    if (t0 >= tend) return;

    // precomputed swizzled offsets
    const uint32_t arow = lane & 15, agrp = (lane >> 4) * 16;
    uint32_t aoff[4][2], boff[4][2];
    #pragma unroll
    for (int kc = 0; kc < 4; ++kc) {
        #pragma unroll
        for (int mi = 0; mi < 2; ++mi)
            aoff[kc][mi] = sw128((uint32_t)((m0 + mi * 16 + arow) * 128 + kc * 32) + agrp);
        #pragma unroll
        for (int ni = 0; ni < 2; ++ni)
            boff[kc][ni] = sw128((uint32_t)((nb0 + ni * 16 + arow) * 128 + kc * 32) + agrp);
    }
    uint32_t so4[4];
    #pragma unroll
    for (int j = 0; j < 4; ++j)
        so4[j] = sw128((uint32_t)(frow * 128 + (fhalf * 4 + j) * 16));

    auto issuePairs = [&](int tt, int ps) {
        if (tid < 64)
            cpa16(sb + SCP(ps) + tid * 16,
                  (const char*)(g_pairs + (size_t)tt * 128) + tid * 16, 16);
    };
    auto issueA = [&](int s, int ps) {
        const int2* prs = (const int2*)(smem + SCP(ps));
        int in = prs[frow].y;
        uint32_t sz = (in >= 0) ? 16u : 0u;
        int ic = (in >= 0) ? in : 0;
        const char* sh = (const char*)(xhi + (size_t)ic * 8);
        const char* sl = (const char*)(xlo + (size_t)ic * 8);
        #pragma unroll
        for (int j = 0; j < 4; ++j) {
            int c = fhalf * 4 + j;
            cpa16(sb + SCA(s) + so4[j], sh + c * 16, sz);
            cpa16(sb + SCA(s) + 16384 + so4[j], sl + c * 16, sz);
        }
    };
    auto issueW = [&](int k) {
        const char* ws = (const char*)(wt + (size_t)k * 1024);
        #pragma unroll
        for (int j = 0; j < 2; ++j) {
            int c = tid + j * 256;
            cpa16(sb + SCW + c * 16, ws + c * 16, 16);
            cpa16(sb + SCW + 8192 + c * 16, ws + 8192 + c * 16, 16);
        }
    };

    // tap of first tile (uniform across block)
    int kk = 0;
    while (stb[kk + 1] <= t0) ++kk;
    int tap = kk + (kk >= 13 ? 1 : 0);

    // prologue
    issuePairs(t0, 0);
    if (t0 + 1 < tend) issuePairs(t0 + 1, 1);
    CP_COMMIT(); CP_WAIT0();
    __syncthreads();
    issueA(0, 0);
    issueW(tap);
    CP_COMMIT();

    const int rq = lane >> 2, cq = (lane & 3) * 2;
    int i = 0;
    for (int t = t0; ; ++t, ++i) {
        const int s = i & 1;
        const int ps = i % 3;
        CP_WAIT0();
        __syncthreads();

        const int tn = t + 1;
        const bool hn = (tn < tend);
        int ntap = tap;
        bool tapchg = false;
        if (hn) {
            while (stb[kk + 1] <= tn) ++kk;
            ntap = kk + (kk >= 13 ? 1 : 0);
            tapchg = (ntap != tap);
            if (!tapchg) {
                issueA(s ^ 1, (i + 1) % 3);
                if (t + 2 < tend) issuePairs(t + 2, (i + 2) % 3);
                CP_COMMIT();
            }
        }

        float acc[2][4][4];
        #pragma unroll
        for (int a = 0; a < 2; ++a)
            #pragma unroll
            for (int b = 0; b < 4; ++b)
                #pragma unroll
                for (int q = 0; q < 4; ++q) acc[a][b][q] = 0.f;

        tile_mma(sb + SCA(s), sb + SCA(s) + 16384, sb + SCW, sb + SCW + 8192,
                 aoff, boff, acc);

        const int2* prs = (const int2*)(smem + SCP(ps));
        #pragma unroll
        for (int mi = 0; mi < 2; ++mi) {
            int r = m0 + mi * 16 + rq;
            int2 p0 = prs[r];
            int2 p1 = prs[r + 8];
            float* o0 = out + (size_t)p0.x * CCH;
            float* o1 = out + (size_t)p1.x * CCH;
            #pragma unroll
            for (int nt = 0; nt < 4; ++nt) {
                int col = nb0 + nt * 8 + cq;
                if (p0.y >= 0) {
                    redadd(o0 + col, acc[mi][nt][0]);
                    redadd(o0 + col + 1, acc[mi][nt][1]);
                }
                if (p1.y >= 0) {
                    redadd(o1 + col, acc[mi][nt][2]);
                    redadd(o1 + col + 1, acc[mi][nt][3]);
                }
            }
        }

        if (!hn) break;
        if (tapchg) {
            __syncthreads();            // all warps finished reading W
            issueA(s ^ 1, (i + 1) % 3);
            issueW(ntap);
            if (t + 2 < tend) issuePairs(t + 2, (i + 2) % 3);
            CP_COMMIT();
            tap = ntap;
        }
    }
}

// ---------------- weight prep: transpose + bf16 split + swizzle --------------
__global__ __launch_bounds__(256) void wprep_kernel(const float* __restrict__ W,
                                                    uint4* __restrict__ wt)
{
    const int k = blockIdx.x;
    char* dst = (char*)(wt + (size_t)k * 1024);
    for (int e = threadIdx.x; e < CCH * CCH; e += 256) {
        int ci = e >> 6, co = e & 63;
        float w = W[(size_t)k * CCH * CCH + e];
        __nv_bfloat16 h = __float2bfloat16(w);
        __nv_bfloat16 l = __float2bfloat16(w - __bfloat162float(h));
        uint32_t off = sw128((uint32_t)(co * 128 + ci * 2));
        *(__nv_bfloat16*)(dst + off) = h;
        *(__nv_bfloat16*)(dst + 8192 + off) = l;
    }
}

// ---------------- split fp32 -> bf16 hi/lo ------------------------------------
__device__ __forceinline__ void split8(const float4& a, const float4& b,
                                       uint4& h, uint4& l)
{
    __nv_bfloat162 h0 = __floats2bfloat162_rn(a.x, a.y);
    __nv_bfloat162 h1 = __floats2bfloat162_rn(a.z, a.w);
    __nv_bfloat162 h2 = __floats2bfloat162_rn(b.x, b.y);
    __nv_bfloat162 h3 = __floats2bfloat162_rn(b.z, b.w);
    float2 f0 = __bfloat1622float2(h0), f1 = __bfloat1622float2(h1);
    float2 f2 = __bfloat1622float2(h2), f3 = __bfloat1622float2(h3);
    __nv_bfloat162 l0 = __floats2bfloat162_rn(a.x - f0.x, a.y - f0.y);
    __nv_bfloat162 l1 = __floats2bfloat162_rn(a.z - f1.x, a.w - f1.y);
    __nv_bfloat162 l2 = __floats2bfloat162_rn(b.x - f2.x, b.y - f2.y);
    __nv_bfloat162 l3 = __floats2bfloat162_rn(b.z - f3.x, b.w - f3.y);
    h = make_uint4(*(uint32_t*)&h0, *(uint32_t*)&h1, *(uint32_t*)&h2, *(uint32_t*)&h3);
    l = make_uint4(*(uint32_t*)&l0, *(uint32_t*)&l1, *(uint32_t*)&l2, *(uint32_t*)&l3);
}

__global__ __launch_bounds__(256) void xprep_kernel(const float* __restrict__ x, int nchunk)
{
    int i = blockIdx.x * blockDim.x + threadIdx.x;
    if (i >= nchunk) return;
    const float4* x4 = (const float4*)x;
    float4 a = x4[2 * i], b = x4[2 * i + 1];
    uint4 h, l;
    split8(a, b, h, l);
    g_xhi[i] = h; g_xlo[i] = l;
}

__global__ __launch_bounds__(256) void bnrelu_kernel(const float* __restrict__ x, int nchunk)
{
    int i = blockIdx.x * blockDim.x + threadIdx.x;
    if (i >= nchunk) return;
    const float4* x4 = (const float4*)x;
    float4 a = x4[2 * i], b = x4[2 * i + 1];
    int c = (i * 8) & 63;
    a.x = fmaxf(a.x * g_stats[c + 0] + g_stats[64 + c + 0], 0.f);
    a.y = fmaxf(a.y * g_stats[c + 1] + g_stats[64 + c + 1], 0.f);
    a.z = fmaxf(a.z * g_stats[c + 2] + g_stats[64 + c + 2], 0.f);
    a.w = fmaxf(a.w * g_stats[c + 3] + g_stats[64 + c + 3], 0.f);
    b.x = fmaxf(b.x * g_stats[c + 4] + g_stats[64 + c + 4], 0.f);
    b.y = fmaxf(b.y * g_stats[c + 5] + g_stats[64 + c + 5], 0.f);
    b.z = fmaxf(b.z * g_stats[c + 6] + g_stats[64 + c + 6], 0.f);
    b.w = fmaxf(b.w * g_stats[c + 7] + g_stats[64 + c + 7], 0.f);
    uint4 h, l;
    split8(a, b, h, l);
    g_xhi[i] = h; g_xlo[i] = l;
}

// ---------------- BN stats (deterministic) ------------------------------------
__global__ __launch_bounds__(256) void stats_kernel(const float* __restrict__ buf, int n)
{
    __shared__ float s[4][128];
    const int tid = threadIdx.x, lane = tid & 63, grp = tid >> 6;
    const int chunk = (n + SBLK - 1) / SBLK;
    const int r0 = blockIdx.x * chunk;
    const int r1 = min(r0 + chunk, n);
    float sm = 0.f, sq = 0.f;
    for (int r = r0 + grp; r < r1; r += 4) {
        float v = buf[(size_t)r * CCH + lane];
        sm += v; sq += v * v;
    }
    s[grp][lane] = sm; s[grp][64 + lane] = sq;
    __syncthreads();
    if (tid < 128)
        g_part[(size_t)blockIdx.x * 128 + tid] = s[0][tid] + s[1][tid] + s[2][tid] + s[3][tid];
}

__global__ __launch_bounds__(512) void reduce_kernel(
    const float* __restrict__ gamma, const float* __restrict__ beta, int n)
{
    __shared__ float s[4][128];
    const int tid = threadIdx.x, col = tid & 127, grp = tid >> 7;
    float acc = 0.f;
    for (int b = grp; b < SBLK; b += 4) acc += g_part[(size_t)b * 128 + col];
    s[grp][col] = acc;
    __syncthreads();
    if (tid < 128) s[0][tid] = s[0][tid] + s[1][tid] + s[2][tid] + s[3][tid];
    __syncthreads();
    if (tid < 64) {
        float inv_n = 1.0f / (float)n;
        float mean = s[0][tid] * inv_n;
        float var = s[0][64 + tid] * inv_n - mean * mean;
        float scale = gamma[tid] * rsqrtf(var + 1e-5f);
        g_stats[tid] = scale;
        g_stats[64 + tid] = beta[tid] - mean * scale;
    }
}

// ---------------- final: BN2 + residual + ReLU --------------------------------
__global__ __launch_bounds__(256) void final_kernel(
    const float* __restrict__ x, const float* __restrict__ feat,
    float* __restrict__ y, int total4)
{
    int i = blockIdx.x * blockDim.x + threadIdx.x;
    if (i >= total4) return;
    float4 v = reinterpret_cast<const float4*>(x)[i];
    float4 f = reinterpret_cast<const float4*>(feat)[i];
    int c = (i * 4) & 63;
    float4 o;
    o.x = fmaxf(v.x * g_stats[c + 0] + g_stats[64 + c + 0] + f.x, 0.f);
    o.y = fmaxf(v.y * g_stats[c + 1] + g_stats[64 + c + 1] + f.y, 0.f);
    o.z = fmaxf(v.z * g_stats[c + 2] + g_stats[64 + c + 2] + f.z, 0.f);
    o.w = fmaxf(v.w * g_stats[c + 3] + g_stats[64 + c + 3] + f.w, 0.f);
    reinterpret_cast<float4*>(y)[i] = o;
}

// ---------------- launch ------------------------------------------------------
extern "C" void kernel_launch(void* const* d_in, const int* in_sizes, int n_in,
                              void* d_out, int out_size)
{
    const float* feat   = (const float*)d_in[0];
    const int*   nbr    = (const int*)  d_in[1];
    const float* valid  = (const float*)d_in[2];
    const float* W1     = (const float*)d_in[3];
    const float* gamma1 = (const float*)d_in[4];
    const float* beta1  = (const float*)d_in[5];
    const float* W2     = (const float*)d_in[6];
    const float* gamma2 = (const float*)d_in[7];
    const float* beta2  = (const float*)d_in[8];
    float* out = (float*)d_out;

    const int n = in_sizes[0] / CCH;
    const int nchunk = n * 8;
    const int total4 = (n * CCH) / 4;

    float *buf1; uint4 *xhi, *xlo, *wt1, *wt2;
    cudaGetSymbolAddress((void**)&buf1, g_buf1);
    cudaGetSymbolAddress((void**)&xhi, g_xhi);
    cudaGetSymbolAddress((void**)&xlo, g_xlo);
    cudaGetSymbolAddress((void**)&wt1, g_wt1);
    cudaGetSymbolAddress((void**)&wt2, g_wt2);

    cudaFuncSetAttribute(center_kernel, cudaFuncAttributeMaxDynamicSharedMemorySize, CEN_SMEM);
    cudaFuncSetAttribute(scatter_kernel, cudaFuncAttributeMaxDynamicSharedMemorySize, SC_SMEM);

    dim3 cenGrid((n + 127) / 128);
    dim3 prepGrid((nchunk + 255) / 256);
    dim3 ewGrid((total4 + 255) / 256);

    // prep
    wprep_kernel<<<KTAPS, 256>>>(W1, wt1);
    wprep_kernel<<<KTAPS, 256>>>(W2, wt2);
    xprep_kernel<<<prepGrid, 256>>>(feat, nchunk);

    // geometry compaction (deterministic)
    count_kernel<<<26 * 64, 256>>>(valid, n);
    scan_kernel<<<1, 1024>>>();
    fill_kernel<<<26 * 64, 256>>>(nbr, valid, n);
    pad_kernel<<<26, 128>>>();

    // conv1
    center_kernel<<<cenGrid, 256, CEN_SMEM>>>(xhi, xlo, wt1 + 13 * 1024, buf1, n);
    scatter_kernel<<<NBLK, 256, SC_SMEM>>>(xhi, xlo, wt1, buf1);
    stats_kernel<<<SBLK, 256>>>(buf1, n);
    reduce_kernel<<<1, 512>>>(gamma1, beta1, n);
    bnrelu_kernel<<<prepGrid, 256>>>(buf1, nchunk);

    // conv2
    center_kernel<<<cenGrid, 256, CEN_SMEM>>>(xhi, xlo, wt2 + 13 * 1024, buf1, n);
    scatter_kernel<<<NBLK, 256, SC_SMEM>>>(xhi, xlo, wt2, buf1);
    stats_kernel<<<SBLK, 256>>>(buf1, n);
    reduce_kernel<<<1, 512>>>(gamma2, beta2, n);
    final_kernel<<<ewGrid, 256>>>(buf1, feat, out, total4);
}

// round 7
// speedup vs baseline: 1.1757x; 1.1757x over previous
#include <cuda_runtime.h>
#include <cuda_bf16.h>
#include <cstdint>
#include <math.h>

#define NVOX   500000
#define CCH    64
#define KTAPS  27
#define SBLK   512
#define SCGRID 2048

// ---------------- static device scratch (no allocs allowed) -----------------
__device__ float g_buf1[(size_t)NVOX * CCH];      // conv out fp32 (pre-BN)
__device__ uint4 g_xhi[(size_t)NVOX * 8];         // bf16 hi features [n][64]
__device__ uint4 g_xlo[(size_t)NVOX * 8];         // bf16 lo features [n][64]
__device__ uint4 g_wt1[KTAPS * 1024];             // W1^T bf16 hi/lo, swizzled
__device__ uint4 g_wt2[KTAPS * 1024];             // W2^T bf16 hi/lo, swizzled
__device__ float g_part[SBLK * 128];
__device__ float g_stats[128];
__device__ int2  g_pairs[(size_t)NVOX * KTAPS];   // compacted (out,in), padded/128
__device__ int   g_bcnt[26 * 64];
__device__ int   g_boff[26 * 64];
__device__ int   g_meta[128];   // [0..26]=tile-base prefix (tb[26]=ntiles), [64+kk]=cnt

// ---------------- helpers ----------------------------------------------------
__device__ __forceinline__ uint32_t smem_u32(const void* p) {
    uint32_t a;
    asm("{ .reg .u64 t; cvta.to.shared.u64 t, %1; cvt.u32.u64 %0, t; }" : "=r"(a) : "l"(p));
    return a;
}
__device__ __host__ __forceinline__ uint32_t sw128(uint32_t off) {
    return off ^ ((off >> 3) & 0x70);
}
__device__ __forceinline__ void ldm_x4(uint32_t* r, uint32_t addr) {
    asm volatile("ldmatrix.sync.aligned.m8n8.x4.shared.b16 {%0,%1,%2,%3}, [%4];"
                 : "=r"(r[0]), "=r"(r[1]), "=r"(r[2]), "=r"(r[3]) : "r"(addr));
}
__device__ __forceinline__ void mma_bf16(float* d, const uint32_t* a,
                                         uint32_t b0, uint32_t b1) {
    asm volatile("mma.sync.aligned.m16n8k16.row.col.f32.bf16.bf16.f32 "
                 "{%0,%1,%2,%3}, {%4,%5,%6,%7}, {%8,%9}, {%0,%1,%2,%3};"
                 : "+f"(d[0]), "+f"(d[1]), "+f"(d[2]), "+f"(d[3])
                 : "r"(a[0]), "r"(a[1]), "r"(a[2]), "r"(a[3]), "r"(b0), "r"(b1));
}
__device__ __forceinline__ void cpa16(uint32_t dst, const void* src, uint32_t sz) {
    asm volatile("cp.async.cg.shared.global [%0], [%1], 16, %2;"
                 :: "r"(dst), "l"(src), "r"(sz) : "memory");
}
#define CP_COMMIT() asm volatile("cp.async.commit_group;" ::: "memory")
#define CP_WAIT0()  asm volatile("cp.async.wait_group 0;" ::: "memory")
// 16B vector reduction: one L2 transaction, 4 adds
__device__ __forceinline__ void redadd4(float* p, float x, float y, float z, float w) {
    asm volatile("red.global.v4.f32.add [%0], {%1,%2,%3,%4};"
                 :: "l"(p), "f"(x), "f"(y), "f"(z), "f"(w) : "memory");
}

// shared 3-pass MMA over one 128x64x64 tile (A hi/lo, W hi/lo in smem)
__device__ __forceinline__ void tile_mma(
    uint32_t ab, uint32_t lb, uint32_t wh, uint32_t wl,
    const uint32_t aoff[4][2], const uint32_t boff[4][2], float acc[2][4][4])
{
    #pragma unroll
    for (int kc = 0; kc < 4; ++kc) {
        uint32_t ah[2][4], al[2][4], bh[2][4], bl[2][4];
        #pragma unroll
        for (int mi = 0; mi < 2; ++mi) {
            ldm_x4(ah[mi], ab + aoff[kc][mi]);
            ldm_x4(al[mi], lb + aoff[kc][mi]);
        }
        #pragma unroll
        for (int ni = 0; ni < 2; ++ni) {
            ldm_x4(bh[ni], wh + boff[kc][ni]);
            ldm_x4(bl[ni], wl + boff[kc][ni]);
        }
        #pragma unroll
        for (int mi = 0; mi < 2; ++mi)
            #pragma unroll
            for (int nt = 0; nt < 4; ++nt) {
                int ni = nt >> 1, s = nt & 1;
                mma_bf16(acc[mi][nt], ah[mi], bh[ni][s], bh[ni][s + 2]);
                mma_bf16(acc[mi][nt], ah[mi], bl[ni][s], bl[ni][s + 2]);
                mma_bf16(acc[mi][nt], al[mi], bh[ni][s], bh[ni][s + 2]);
            }
    }
}

// ---------------- compaction: count -> scan -> fill -> pad --------------------
__global__ __launch_bounds__(256) void count_kernel(const float* __restrict__ valid, int n)
{
    const int kk = blockIdx.x >> 6, b = blockIdx.x & 63;
    const int k = kk + (kk >= 13 ? 1 : 0);
    const int chunk = (n + 63) >> 6;
    const int r0 = b * chunk, r1 = min(r0 + chunk, n);
    const int tid = threadIdx.x, lane = tid & 31, wid = tid >> 5;
    int c = 0;
    for (int i = r0 + tid; i < r1; i += 256)
        c += (valid[(size_t)k * n + i] != 0.f);
    #pragma unroll
    for (int d = 16; d > 0; d >>= 1) c += __shfl_down_sync(0xffffffffu, c, d);
    __shared__ int ws[8];
    if (lane == 0) ws[wid] = c;
    __syncthreads();
    if (tid == 0) {
        int t = 0;
        for (int w = 0; w < 8; ++w) t += ws[w];
        g_bcnt[blockIdx.x] = t;
    }
}

__global__ __launch_bounds__(1024) void scan_kernel()
{
    __shared__ int sc[26];
    __shared__ int stb[27];
    const int tid = threadIdx.x, wid = tid >> 5, lane = tid & 31;
    int e0 = 0, e1 = 0;
    if (wid < 26) {
        int v0 = g_bcnt[wid * 64 + lane];
        int v1 = g_bcnt[wid * 64 + 32 + lane];
        int p0 = v0;
        #pragma unroll
        for (int d = 1; d < 32; d <<= 1) {
            int t = __shfl_up_sync(0xffffffffu, p0, d);
            if (lane >= d) p0 += t;
        }
        int tot0 = __shfl_sync(0xffffffffu, p0, 31);
        int p1 = v1;
        #pragma unroll
        for (int d = 1; d < 32; d <<= 1) {
            int t = __shfl_up_sync(0xffffffffu, p1, d);
            if (lane >= d) p1 += t;
        }
        p1 += tot0;
        e0 = p0 - v0;
        e1 = p1 - v1;
        if (lane == 31) sc[wid] = p1;
    }
    __syncthreads();
    if (tid == 0) {
        int tb = 0;
        for (int kk = 0; kk < 26; ++kk) {
            stb[kk] = tb;
            tb += (sc[kk] + 127) >> 7;
            g_meta[64 + kk] = sc[kk];
        }
        stb[26] = tb;
        for (int kk = 0; kk <= 26; ++kk) g_meta[kk] = stb[kk];
    }
    __syncthreads();
    if (wid < 26) {
        int base = stb[wid] * 128;
        g_boff[wid * 64 + lane]      = base + e0;
        g_boff[wid * 64 + 32 + lane] = base + e1;
    }
}

__global__ __launch_bounds__(256) void fill_kernel(
    const int* __restrict__ nbr, const float* __restrict__ valid, int n)
{
    const int kk = blockIdx.x >> 6, b = blockIdx.x & 63;
    const int k = kk + (kk >= 13 ? 1 : 0);
    const int chunk = (n + 63) >> 6;
    const int r0 = b * chunk, r1 = min(r0 + chunk, n);
    const int tid = threadIdx.x, lane = tid & 31, wid = tid >> 5;
    const int base = g_boff[blockIdx.x];
    __shared__ int wb[9];
    int run = 0;
    for (int s = r0; s < r1; s += 256) {
        int i = s + tid;
        bool v = (i < r1) && (valid[(size_t)k * n + i] != 0.f);
        unsigned bal = __ballot_sync(0xffffffffu, v);
        if (lane == 0) wb[wid] = __popc(bal);
        __syncthreads();
        if (tid == 0) {
            int t = 0;
            for (int w = 0; w < 8; ++w) { int x = wb[w]; wb[w] = t; t += x; }
            wb[8] = t;
        }
        __syncthreads();
        if (v) {
            int off = base + run + wb[wid] + __popc(bal & ((1u << lane) - 1u));
            g_pairs[off] = make_int2(i, nbr[(size_t)k * n + i]);
        }
        run += wb[8];
        __syncthreads();
    }
}

__global__ __launch_bounds__(128) void pad_kernel()
{
    const int kk = blockIdx.x;
    const int cnt = g_meta[64 + kk];
    const int base = g_meta[kk] * 128;
    const int padded = (g_meta[kk + 1] - g_meta[kk]) * 128;
    for (int s = cnt + threadIdx.x; s < padded; s += 128)
        g_pairs[base + s] = make_int2(0, -1);
}

// ---------------- center tap: dense GEMM, plain writes ------------------------
#define CEN_SMEM 49152
__global__ __launch_bounds__(256, 2) void center_kernel(
    const uint4* __restrict__ xhi, const uint4* __restrict__ xlo,
    const uint4* __restrict__ wtap, float* __restrict__ out, int n)
{
    extern __shared__ char smem[];
    const uint32_t sb = smem_u32(smem);
    const int tid = threadIdx.x, lane = tid & 31, wid = tid >> 5;
    const int n0 = blockIdx.x * 128;
    const int m0 = (wid & 3) * 32, nb0 = (wid >> 2) * 32;
    const int frow = tid >> 1, fhalf = tid & 1;

    const int g = n0 + frow;
    const uint32_t sz = (g < n) ? 16u : 0u;
    const int gc = min(g, n - 1);
    const char* sh = (const char*)(xhi + (size_t)gc * 8);
    const char* sl = (const char*)(xlo + (size_t)gc * 8);
    #pragma unroll
    for (int j = 0; j < 4; ++j) {
        int c = fhalf * 4 + j;
        uint32_t so = sw128((uint32_t)(frow * 128 + c * 16));
        cpa16(sb + so, sh + c * 16, sz);
        cpa16(sb + 16384 + so, sl + c * 16, sz);
    }
    const char* ws = (const char*)wtap;
    #pragma unroll
    for (int j = 0; j < 2; ++j) {
        int c = tid + j * 256;
        cpa16(sb + 32768 + c * 16, ws + c * 16, 16);
        cpa16(sb + 40960 + c * 16, ws + 8192 + c * 16, 16);
    }
    CP_COMMIT(); CP_WAIT0();
    __syncthreads();

    const uint32_t arow = lane & 15, agrp = (lane >> 4) * 16;
    uint32_t aoff[4][2], boff[4][2];
    #pragma unroll
    for (int kc = 0; kc < 4; ++kc) {
        #pragma unroll
        for (int mi = 0; mi < 2; ++mi)
            aoff[kc][mi] = sw128((uint32_t)((m0 + mi * 16 + arow) * 128 + kc * 32) + agrp);
        #pragma unroll
        for (int ni = 0; ni < 2; ++ni)
            boff[kc][ni] = sw128((uint32_t)((nb0 + ni * 16 + arow) * 128 + kc * 32) + agrp);
    }

    float acc[2][4][4];
    #pragma unroll
    for (int i = 0; i < 2; ++i)
        #pragma unroll
        for (int j = 0; j < 4; ++j)
            #pragma unroll
            for (int q = 0; q < 4; ++q) acc[i][j][q] = 0.f;

    tile_mma(sb, sb + 16384, sb + 32768, sb + 40960, aoff, boff, acc);

    const int rq = lane >> 2, cq = (lane & 3) * 2;
    #pragma unroll
    for (int mi = 0; mi < 2; ++mi)
        #pragma unroll
        for (int nt = 0; nt < 4; ++nt) {
            int col = nb0 + nt * 8 + cq;
            int r0 = n0 + m0 + mi * 16 + rq;
            if (r0 < n)
                *(float2*)(out + (size_t)r0 * CCH + col) = make_float2(acc[mi][nt][0], acc[mi][nt][1]);
            int r1 = r0 + 8;
            if (r1 < n)
                *(float2*)(out + (size_t)r1 * CCH + col) = make_float2(acc[mi][nt][2], acc[mi][nt][3]);
        }
}

// ---------------- scatter conv: compacted tiles + vector RED ------------------
#define SCA(s)     ((s) * 32768)            // hi 16KB + lo 16KB
#define SCW(s)     (65536 + (s) * 16384)    // hi 8KB + lo 8KB
#define SCP(ps)    (98304 + (ps) * 1024)    // pairs, 3 stages
#define SC_TB      101376
#define SC_SMEM    101504

__global__ __launch_bounds__(256, 2) void scatter_kernel(
    const uint4* __restrict__ xhi, const uint4* __restrict__ xlo,
    const uint4* __restrict__ wt, float* __restrict__ out)
{
    extern __shared__ char smem[];
    const uint32_t sb = smem_u32(smem);
    const int tid = threadIdx.x, lane = tid & 31, wid = tid >> 5;
    const int m0 = (wid & 3) * 32, nb0 = (wid >> 2) * 32;
    const int frow = tid >> 1, fhalf = tid & 1;

    int* stb = (int*)(smem + SC_TB);
    if (tid < 27) stb[tid] = g_meta[tid];
    __syncthreads();
    const int ntiles = stb[26];

    int t = blockIdx.x;
    if (t >= ntiles) return;

    // precomputed offsets
    const uint32_t arow = lane & 15, agrp = (lane >> 4) * 16;
    uint32_t aoff[4][2], boff[4][2];
    #pragma unroll
    for (int kc = 0; kc < 4; ++kc) {
        #pragma unroll
        for (int mi = 0; mi < 2; ++mi)
            aoff[kc][mi] = sw128((uint32_t)((m0 + mi * 16 + arow) * 128 + kc * 32) + agrp);
        #pragma unroll
        for (int ni = 0; ni < 2; ++ni)
            boff[kc][ni] = sw128((uint32_t)((nb0 + ni * 16 + arow) * 128 + kc * 32) + agrp);
    }
    uint32_t so4[4];
    #pragma unroll
    for (int j = 0; j < 4; ++j)
        so4[j] = sw128((uint32_t)(frow * 128 + (fhalf * 4 + j) * 16));

    auto tapof = [&](int tt) {
        int kk = 0;
        while (kk < 25 && tt >= stb[kk + 1]) ++kk;
        return kk + (kk >= 13 ? 1 : 0);
    };
    auto issuePairs = [&](int tt, int ps) {
        if (tid < 64)
            cpa16(sb + SCP(ps) + tid * 16,
                  (const char*)(g_pairs + (size_t)tt * 128) + tid * 16, 16);
    };
    auto issueA = [&](int s, int ps) {
        const int2* prs = (const int2*)(smem + SCP(ps));
        int in = prs[frow].y;
        uint32_t sz = (in >= 0) ? 16u : 0u;
        int ic = (in >= 0) ? in : 0;
        const char* sh = (const char*)(xhi + (size_t)ic * 8);
        const char* sl = (const char*)(xlo + (size_t)ic * 8);
        #pragma unroll
        for (int j = 0; j < 4; ++j) {
            int c = fhalf * 4 + j;
            cpa16(sb + SCA(s) + so4[j], sh + c * 16, sz);
            cpa16(sb + SCA(s) + 16384 + so4[j], sl + c * 16, sz);
        }
    };
    auto issueW = [&](int s, int k) {
        const char* ws = (const char*)(wt + (size_t)k * 1024);
        #pragma unroll
        for (int j = 0; j < 2; ++j) {
            int c = tid + j * 256;
            cpa16(sb + SCW(s) + c * 16, ws + c * 16, 16);
            cpa16(sb + SCW(s) + 8192 + c * 16, ws + 8192 + c * 16, 16);
        }
    };

    // prologue: pairs(t0), pairs(t1); then A/W(t0)
    issuePairs(t, 0);
    int t1 = t + SCGRID;
    if (t1 < ntiles) issuePairs(t1, 1);
    CP_COMMIT(); CP_WAIT0();
    __syncthreads();
    issueA(0, 0);
    issueW(0, tapof(t));
    CP_COMMIT();

    const int rq = lane >> 2;
    const int cb = (lane & 2) * 2;       // 0 or 4: v4 column base within 8-col tile
    const bool evn = !(lane & 1);
    int i = 0;
    while (true) {
        const int s = i & 1;
        const int ps = i % 3;
        CP_WAIT0();
        __syncthreads();

        int tn = t + SCGRID;
        bool hn = (tn < ntiles);
        if (hn) {
            issueA(s ^ 1, (i + 1) % 3);
            issueW(s ^ 1, tapof(tn));
            int tn2 = tn + SCGRID;
            if (tn2 < ntiles) issuePairs(tn2, (i + 2) % 3);
            CP_COMMIT();
        }

        float acc[2][4][4];
        #pragma unroll
        for (int a = 0; a < 2; ++a)
            #pragma unroll
            for (int b = 0; b < 4; ++b)
                #pragma unroll
                for (int q = 0; q < 4; ++q) acc[a][b][q] = 0.f;

        tile_mma(sb + SCA(s), sb + SCA(s) + 16384, sb + SCW(s), sb + SCW(s) + 8192,
                 aoff, boff, acc);

        // epilogue: butterfly lanes (l, l^1) to form 16B vectors, one v4 RED each
        const int2* prs = (const int2*)(smem + SCP(ps));
        #pragma unroll
        for (int mi = 0; mi < 2; ++mi) {
            int r = m0 + mi * 16 + rq;
            int2 p0 = prs[r];         // row r (lanes l and l^1 agree)
            int2 p1 = prs[r + 8];     // row r+8
            float* o0 = out + (size_t)p0.x * CCH;
            float* o1 = out + (size_t)p1.x * CCH;
            #pragma unroll
            for (int nt = 0; nt < 4; ++nt) {
                float a0 = acc[mi][nt][0], a1 = acc[mi][nt][1];
                float a2 = acc[mi][nt][2], a3 = acc[mi][nt][3];
                float b0 = __shfl_xor_sync(0xffffffffu, a0, 1);
                float b1 = __shfl_xor_sync(0xffffffffu, a1, 1);
                float b2 = __shfl_xor_sync(0xffffffffu, a2, 1);
                float b3 = __shfl_xor_sync(0xffffffffu, a3, 1);
                int col = nb0 + nt * 8 + cb;
                if (evn) {
                    if (p0.y >= 0) redadd4(o0 + col, a0, a1, b0, b1);
                } else {
                    if (p1.y >= 0) redadd4(o1 + col, b2, b3, a2, a3);
                }
            }
        }
        if (!hn) break;
        t = tn;
        ++i;
    }
}

// ---------------- weight prep: transpose + bf16 split + swizzle --------------
__global__ __launch_bounds__(256) void wprep_kernel(const float* __restrict__ W,
                                                    uint4* __restrict__ wt)
{
    const int k = blockIdx.x;
    char* dst = (char*)(wt + (size_t)k * 1024);
    for (int e = threadIdx.x; e < CCH * CCH; e += 256) {
        int ci = e >> 6, co = e & 63;
        float w = W[(size_t)k * CCH * CCH + e];
        __nv_bfloat16 h = __float2bfloat16(w);
        __nv_bfloat16 l = __float2bfloat16(w - __bfloat162float(h));
        uint32_t off = sw128((uint32_t)(co * 128 + ci * 2));
        *(__nv_bfloat16*)(dst + off) = h;
        *(__nv_bfloat16*)(dst + 8192 + off) = l;
    }
}

// ---------------- split fp32 -> bf16 hi/lo ------------------------------------
__device__ __forceinline__ void split8(const float4& a, const float4& b,
                                       uint4& h, uint4& l)
{
    __nv_bfloat162 h0 = __floats2bfloat162_rn(a.x, a.y);
    __nv_bfloat162 h1 = __floats2bfloat162_rn(a.z, a.w);
    __nv_bfloat162 h2 = __floats2bfloat162_rn(b.x, b.y);
    __nv_bfloat162 h3 = __floats2bfloat162_rn(b.z, b.w);
    float2 f0 = __bfloat1622float2(h0), f1 = __bfloat1622float2(h1);
    float2 f2 = __bfloat1622float2(h2), f3 = __bfloat1622float2(h3);
    __nv_bfloat162 l0 = __floats2bfloat162_rn(a.x - f0.x, a.y - f0.y);
    __nv_bfloat162 l1 = __floats2bfloat162_rn(a.z - f1.x, a.w - f1.y);
    __nv_bfloat162 l2 = __floats2bfloat162_rn(b.x - f2.x, b.y - f2.y);
    __nv_bfloat162 l3 = __floats2bfloat162_rn(b.z - f3.x, b.w - f3.y);
    h = make_uint4(*(uint32_t*)&h0, *(uint32_t*)&h1, *(uint32_t*)&h2, *(uint32_t*)&h3);
    l = make_uint4(*(uint32_t*)&l0, *(uint32_t*)&l1, *(uint32_t*)&l2, *(uint32_t*)&l3);
}

__global__ __launch_bounds__(256) void xprep_kernel(const float* __restrict__ x, int nchunk)
{
    int i = blockIdx.x * blockDim.x + threadIdx.x;
    if (i >= nchunk) return;
    const float4* x4 = (const float4*)x;
    float4 a = x4[2 * i], b = x4[2 * i + 1];
    uint4 h, l;
    split8(a, b, h, l);
    g_xhi[i] = h; g_xlo[i] = l;
}

__global__ __launch_bounds__(256) void bnrelu_kernel(const float* __restrict__ x, int nchunk)
{
    int i = blockIdx.x * blockDim.x + threadIdx.x;
    if (i >= nchunk) return;
    const float4* x4 = (const float4*)x;
    float4 a = x4[2 * i], b = x4[2 * i + 1];
    int c = (i * 8) & 63;
    a.x = fmaxf(a.x * g_stats[c + 0] + g_stats[64 + c + 0], 0.f);
    a.y = fmaxf(a.y * g_stats[c + 1] + g_stats[64 + c + 1], 0.f);
    a.z = fmaxf(a.z * g_stats[c + 2] + g_stats[64 + c + 2], 0.f);
    a.w = fmaxf(a.w * g_stats[c + 3] + g_stats[64 + c + 3], 0.f);
    b.x = fmaxf(b.x * g_stats[c + 4] + g_stats[64 + c + 4], 0.f);
    b.y = fmaxf(b.y * g_stats[c + 5] + g_stats[64 + c + 5], 0.f);
    b.z = fmaxf(b.z * g_stats[c + 6] + g_stats[64 + c + 6], 0.f);
    b.w = fmaxf(b.w * g_stats[c + 7] + g_stats[64 + c + 7], 0.f);
    uint4 h, l;
    split8(a, b, h, l);
    g_xhi[i] = h; g_xlo[i] = l;
}

// ---------------- BN stats (deterministic) ------------------------------------
__global__ __launch_bounds__(256) void stats_kernel(const float* __restrict__ buf, int n)
{
    __shared__ float s[4][128];
    const int tid = threadIdx.x, lane = tid & 63, grp = tid >> 6;
    const int chunk = (n + SBLK - 1) / SBLK;
    const int r0 = blockIdx.x * chunk;
    const int r1 = min(r0 + chunk, n);
    float sm = 0.f, sq = 0.f;
    for (int r = r0 + grp; r < r1; r += 4) {
        float v = buf[(size_t)r * CCH + lane];
        sm += v; sq += v * v;
    }
    s[grp][lane] = sm; s[grp][64 + lane] = sq;
    __syncthreads();
    if (tid < 128)
        g_part[(size_t)blockIdx.x * 128 + tid] = s[0][tid] + s[1][tid] + s[2][tid] + s[3][tid];
}

__global__ __launch_bounds__(512) void reduce_kernel(
    const float* __restrict__ gamma, const float* __restrict__ beta, int n)
{
    __shared__ float s[4][128];
    const int tid = threadIdx.x, col = tid & 127, grp = tid >> 7;
    float acc = 0.f;
    for (int b = grp; b < SBLK; b += 4) acc += g_part[(size_t)b * 128 + col];
    s[grp][col] = acc;
    __syncthreads();
    if (tid < 128) s[0][tid] = s[0][tid] + s[1][tid] + s[2][tid] + s[3][tid];
    __syncthreads();
    if (tid < 64) {
        float inv_n = 1.0f / (float)n;
        float mean = s[0][tid] * inv_n;
        float var = s[0][64 + tid] * inv_n - mean * mean;
        float scale = gamma[tid] * rsqrtf(var + 1e-5f);
        g_stats[tid] = scale;
        g_stats[64 + tid] = beta[tid] - mean * scale;
    }
}

// ---------------- final: BN2 + residual + ReLU --------------------------------
__global__ __launch_bounds__(256) void final_kernel(
    const float* __restrict__ x, const float* __restrict__ feat,
    float* __restrict__ y, int total4)
{
    int i = blockIdx.x * blockDim.x + threadIdx.x;
    if (i >= total4) return;
    float4 v = reinterpret_cast<const float4*>(x)[i];
    float4 f = reinterpret_cast<const float4*>(feat)[i];
    int c = (i * 4) & 63;
    float4 o;
    o.x = fmaxf(v.x * g_stats[c + 0] + g_stats[64 + c + 0] + f.x, 0.f);
    o.y = fmaxf(v.y * g_stats[c + 1] + g_stats[64 + c + 1] + f.y, 0.f);
    o.z = fmaxf(v.z * g_stats[c + 2] + g_stats[64 + c + 2] + f.z, 0.f);
    o.w = fmaxf(v.w * g_stats[c + 3] + g_stats[64 + c + 3] + f.w, 0.f);
    reinterpret_cast<float4*>(y)[i] = o;
}

// ---------------- launch ------------------------------------------------------
extern "C" void kernel_launch(void* const* d_in, const int* in_sizes, int n_in,
                              void* d_out, int out_size)
{
    const float* feat   = (const float*)d_in[0];
    const int*   nbr    = (const int*)  d_in[1];
    const float* valid  = (const float*)d_in[2];
    const float* W1     = (const float*)d_in[3];
    const float* gamma1 = (const float*)d_in[4];
    const float* beta1  = (const float*)d_in[5];
    const float* W2     = (const float*)d_in[6];
    const float* gamma2 = (const float*)d_in[7];
    const float* beta2  = (const float*)d_in[8];
    float* out = (float*)d_out;

    const int n = in_sizes[0] / CCH;
    const int nchunk = n * 8;
    const int total4 = (n * CCH) / 4;

    float *buf1; uint4 *xhi, *xlo, *wt1, *wt2;
    cudaGetSymbolAddress((void**)&buf1, g_buf1);
    cudaGetSymbolAddress((void**)&xhi, g_xhi);
    cudaGetSymbolAddress((void**)&xlo, g_xlo);
    cudaGetSymbolAddress((void**)&wt1, g_wt1);
    cudaGetSymbolAddress((void**)&wt2, g_wt2);

    cudaFuncSetAttribute(center_kernel, cudaFuncAttributeMaxDynamicSharedMemorySize, CEN_SMEM);
    cudaFuncSetAttribute(scatter_kernel, cudaFuncAttributeMaxDynamicSharedMemorySize, SC_SMEM);

    dim3 cenGrid((n + 127) / 128);
    dim3 prepGrid((nchunk + 255) / 256);
    dim3 ewGrid((total4 + 255) / 256);

    // prep
    wprep_kernel<<<KTAPS, 256>>>(W1, wt1);
    wprep_kernel<<<KTAPS, 256>>>(W2, wt2);
    xprep_kernel<<<prepGrid, 256>>>(feat, nchunk);

    // geometry compaction (deterministic)
    count_kernel<<<26 * 64, 256>>>(valid, n);
    scan_kernel<<<1, 1024>>>();
    fill_kernel<<<26 * 64, 256>>>(nbr, valid, n);
    pad_kernel<<<26, 128>>>();

    // conv1
    center_kernel<<<cenGrid, 256, CEN_SMEM>>>(xhi, xlo, wt1 + 13 * 1024, buf1, n);
    scatter_kernel<<<SCGRID, 256, SC_SMEM>>>(xhi, xlo, wt1, buf1);
    stats_kernel<<<SBLK, 256>>>(buf1, n);
    reduce_kernel<<<1, 512>>>(gamma1, beta1, n);
    bnrelu_kernel<<<prepGrid, 256>>>(buf1, nchunk);

    // conv2
    center_kernel<<<cenGrid, 256, CEN_SMEM>>>(xhi, xlo, wt2 + 13 * 1024, buf1, n);
    scatter_kernel<<<SCGRID, 256, SC_SMEM>>>(xhi, xlo, wt2, buf1);
    stats_kernel<<<SBLK, 256>>>(buf1, n);
    reduce_kernel<<<1, 512>>>(gamma2, beta2, n);
    final_kernel<<<ewGrid, 256>>>(buf1, feat, out, total4);
}

// round 10
// speedup vs baseline: 1.2050x; 1.0250x over previous
#include <cuda_runtime.h>
#include <cuda_bf16.h>
#include <cstdint>
#include <math.h>

#define NVOX   500000
#define CCH    64
#define KTAPS  27
#define SBLK   512
#define SCGRID 2048

// ---------------- static device scratch (no allocs allowed) -----------------
__device__ float g_buf1[(size_t)NVOX * CCH];      // conv out fp32 (pre-BN)
__device__ uint4 g_xhi[(size_t)NVOX * 8];         // bf16 hi features [n][64]
__device__ uint4 g_xlo[(size_t)NVOX * 8];         // bf16 lo features [n][64]
__device__ uint4 g_wt1[KTAPS * 1024];             // W1^T bf16 hi/lo, swizzled
__device__ uint4 g_wt2[KTAPS * 1024];             // W2^T bf16 hi/lo, swizzled
__device__ float g_part[SBLK * 128];
__device__ float g_stats[128];
__device__ int2  g_pairs[(size_t)NVOX * KTAPS];   // compacted (out,in), padded/128
__device__ int   g_bcnt[26 * 64];
__device__ int   g_boff[26 * 64];
__device__ int   g_meta[128];   // [0..26]=tile-base prefix (tb[26]=ntiles), [64+kk]=cnt

// ---------------- helpers ----------------------------------------------------
__device__ __forceinline__ uint32_t smem_u32(const void* p) {
    uint32_t a;
    asm("{ .reg .u64 t; cvta.to.shared.u64 t, %1; cvt.u32.u64 %0, t; }" : "=r"(a) : "l"(p));
    return a;
}
__device__ __host__ __forceinline__ uint32_t sw128(uint32_t off) {
    return off ^ ((off >> 3) & 0x70);
}
__device__ __forceinline__ void ldm_x4(uint32_t* r, uint32_t addr) {
    asm volatile("ldmatrix.sync.aligned.m8n8.x4.shared.b16 {%0,%1,%2,%3}, [%4];"
                 : "=r"(r[0]), "=r"(r[1]), "=r"(r[2]), "=r"(r[3]) : "r"(addr));
}
__device__ __forceinline__ void mma_bf16(float* d, const uint32_t* a,
                                         uint32_t b0, uint32_t b1) {
    asm volatile("mma.sync.aligned.m16n8k16.row.col.f32.bf16.bf16.f32 "
                 "{%0,%1,%2,%3}, {%4,%5,%6,%7}, {%8,%9}, {%0,%1,%2,%3};"
                 : "+f"(d[0]), "+f"(d[1]), "+f"(d[2]), "+f"(d[3])
                 : "r"(a[0]), "r"(a[1]), "r"(a[2]), "r"(a[3]), "r"(b0), "r"(b1));
}
__device__ __forceinline__ void cpa16(uint32_t dst, const void* src, uint32_t sz) {
    asm volatile("cp.async.cg.shared.global [%0], [%1], 16, %2;"
                 :: "r"(dst), "l"(src), "r"(sz) : "memory");
}
#define CP_COMMIT() asm volatile("cp.async.commit_group;" ::: "memory")
#define CP_WAIT0()  asm volatile("cp.async.wait_group 0;" ::: "memory")
// 16B vector reduction: one L2 transaction, 4 adds
__device__ __forceinline__ void redadd4(float* p, float x, float y, float z, float w) {
    asm volatile("red.global.v4.f32.add [%0], {%1,%2,%3,%4};"
                 :: "l"(p), "f"(x), "f"(y), "f"(z), "f"(w) : "memory");
}

// shared 3-pass MMA over one 128x64x64 tile (A hi/lo, W hi/lo in smem)
__device__ __forceinline__ void tile_mma(
    uint32_t ab, uint32_t lb, uint32_t wh, uint32_t wl,
    const uint32_t aoff[4][2], const uint32_t boff[4][2], float acc[2][4][4])
{
    #pragma unroll
    for (int kc = 0; kc < 4; ++kc) {
        uint32_t ah[2][4], al[2][4], bh[2][4], bl[2][4];
        #pragma unroll
        for (int mi = 0; mi < 2; ++mi) {
            ldm_x4(ah[mi], ab + aoff[kc][mi]);
            ldm_x4(al[mi], lb + aoff[kc][mi]);
        }
        #pragma unroll
        for (int ni = 0; ni < 2; ++ni) {
            ldm_x4(bh[ni], wh + boff[kc][ni]);
            ldm_x4(bl[ni], wl + boff[kc][ni]);
        }
        #pragma unroll
        for (int mi = 0; mi < 2; ++mi)
            #pragma unroll
            for (int nt = 0; nt < 4; ++nt) {
                int ni = nt >> 1, s = nt & 1;
                mma_bf16(acc[mi][nt], ah[mi], bh[ni][s], bh[ni][s + 2]);
                mma_bf16(acc[mi][nt], ah[mi], bl[ni][s], bl[ni][s + 2]);
                mma_bf16(acc[mi][nt], al[mi], bh[ni][s], bh[ni][s + 2]);
            }
    }
}

// ---------------- split fp32 -> bf16 hi/lo ------------------------------------
__device__ __forceinline__ void split8(const float4& a, const float4& b,
                                       uint4& h, uint4& l)
{
    __nv_bfloat162 h0 = __floats2bfloat162_rn(a.x, a.y);
    __nv_bfloat162 h1 = __floats2bfloat162_rn(a.z, a.w);
    __nv_bfloat162 h2 = __floats2bfloat162_rn(b.x, b.y);
    __nv_bfloat162 h3 = __floats2bfloat162_rn(b.z, b.w);
    float2 f0 = __bfloat1622float2(h0), f1 = __bfloat1622float2(h1);
    float2 f2 = __bfloat1622float2(h2), f3 = __bfloat1622float2(h3);
    __nv_bfloat162 l0 = __floats2bfloat162_rn(a.x - f0.x, a.y - f0.y);
    __nv_bfloat162 l1 = __floats2bfloat162_rn(a.z - f1.x, a.w - f1.y);
    __nv_bfloat162 l2 = __floats2bfloat162_rn(b.x - f2.x, b.y - f2.y);
    __nv_bfloat162 l3 = __floats2bfloat162_rn(b.z - f3.x, b.w - f3.y);
    h = make_uint4(*(uint32_t*)&h0, *(uint32_t*)&h1, *(uint32_t*)&h2, *(uint32_t*)&h3);
    l = make_uint4(*(uint32_t*)&l0, *(uint32_t*)&l1, *(uint32_t*)&l2, *(uint32_t*)&l3);
}

// ---------------- fused prep: wprep(W1)+wprep(W2)+xprep -----------------------
// blocks 0..26 = W1 taps, 27..53 = W2 taps, 54.. = xprep chunks
__global__ __launch_bounds__(256) void prep_kernel(
    const float* __restrict__ W1, const float* __restrict__ W2,
    const float* __restrict__ x, int nchunk)
{
    const int b = blockIdx.x;
    if (b < 54) {
        const int k = (b < 27) ? b : b - 27;
        const float* W = (b < 27) ? W1 : W2;
        uint4* wt = (b < 27) ? g_wt1 : g_wt2;
        char* dst = (char*)(wt + (size_t)k * 1024);
        for (int e = threadIdx.x; e < CCH * CCH; e += 256) {
            int ci = e >> 6, co = e & 63;
            float w = W[(size_t)k * CCH * CCH + e];
            __nv_bfloat16 h = __float2bfloat16(w);
            __nv_bfloat16 l = __float2bfloat16(w - __bfloat162float(h));
            uint32_t off = sw128((uint32_t)(co * 128 + ci * 2));
            *(__nv_bfloat16*)(dst + off) = h;
            *(__nv_bfloat16*)(dst + 8192 + off) = l;
        }
    } else {
        int i = (b - 54) * 256 + threadIdx.x;
        if (i >= nchunk) return;
        const float4* x4 = (const float4*)x;
        float4 a = x4[2 * i], c = x4[2 * i + 1];
        uint4 h, l;
        split8(a, c, h, l);
        g_xhi[i] = h; g_xlo[i] = l;
    }
}

// ---------------- compaction: count -> scan -> fill(+pad) ---------------------
__global__ __launch_bounds__(256) void count_kernel(const float* __restrict__ valid, int n)
{
    const int kk = blockIdx.x >> 6, b = blockIdx.x & 63;
    const int k = kk + (kk >= 13 ? 1 : 0);
    const int chunk = (n + 63) >> 6;
    const int r0 = b * chunk, r1 = min(r0 + chunk, n);
    const int tid = threadIdx.x, lane = tid & 31, wid = tid >> 5;
    int c = 0;
    for (int i = r0 + tid; i < r1; i += 256)
        c += (valid[(size_t)k * n + i] != 0.f);
    #pragma unroll
    for (int d = 16; d > 0; d >>= 1) c += __shfl_down_sync(0xffffffffu, c, d);
    __shared__ int ws[8];
    if (lane == 0) ws[wid] = c;
    __syncthreads();
    if (tid == 0) {
        int t = 0;
        for (int w = 0; w < 8; ++w) t += ws[w];
        g_bcnt[blockIdx.x] = t;
    }
}

__global__ __launch_bounds__(1024) void scan_kernel()
{
    __shared__ int sc[26];
    __shared__ int stb[27];
    const int tid = threadIdx.x, wid = tid >> 5, lane = tid & 31;
    int e0 = 0, e1 = 0;
    if (wid < 26) {
        int v0 = g_bcnt[wid * 64 + lane];
        int v1 = g_bcnt[wid * 64 + 32 + lane];
        int p0 = v0;
        #pragma unroll
        for (int d = 1; d < 32; d <<= 1) {
            int t = __shfl_up_sync(0xffffffffu, p0, d);
            if (lane >= d) p0 += t;
        }
        int tot0 = __shfl_sync(0xffffffffu, p0, 31);
        int p1 = v1;
        #pragma unroll
        for (int d = 1; d < 32; d <<= 1) {
            int t = __shfl_up_sync(0xffffffffu, p1, d);
            if (lane >= d) p1 += t;
        }
        p1 += tot0;
        e0 = p0 - v0;
        e1 = p1 - v1;
        if (lane == 31) sc[wid] = p1;
    }
    __syncthreads();
    if (tid == 0) {
        int tb = 0;
        for (int kk = 0; kk < 26; ++kk) {
            stb[kk] = tb;
            tb += (sc[kk] + 127) >> 7;
            g_meta[64 + kk] = sc[kk];
        }
        stb[26] = tb;
        for (int kk = 0; kk <= 26; ++kk) g_meta[kk] = stb[kk];
    }
    __syncthreads();
    if (wid < 26) {
        int base = stb[wid] * 128;
        g_boff[wid * 64 + lane]      = base + e0;
        g_boff[wid * 64 + 32 + lane] = base + e1;
    }
}

// fill + (last block of each tap pads the segment tail)
__global__ __launch_bounds__(256) void fill_kernel(
    const int* __restrict__ nbr, const float* __restrict__ valid, int n)
{
    const int kk = blockIdx.x >> 6, b = blockIdx.x & 63;
    const int k = kk + (kk >= 13 ? 1 : 0);
    const int chunk = (n + 63) >> 6;
    const int r0 = b * chunk, r1 = min(r0 + chunk, n);
    const int tid = threadIdx.x, lane = tid & 31, wid = tid >> 5;
    const int base = g_boff[blockIdx.x];
    __shared__ int wb[9];
    int run = 0;
    for (int s = r0; s < r1; s += 256) {
        int i = s + tid;
        bool v = (i < r1) && (valid[(size_t)k * n + i] != 0.f);
        unsigned bal = __ballot_sync(0xffffffffu, v);
        if (lane == 0) wb[wid] = __popc(bal);
        __syncthreads();
        if (tid == 0) {
            int t = 0;
            for (int w = 0; w < 8; ++w) { int x = wb[w]; wb[w] = t; t += x; }
            wb[8] = t;
        }
        __syncthreads();
        if (v) {
            int off = base + run + wb[wid] + __popc(bal & ((1u << lane) - 1u));
            g_pairs[off] = make_int2(i, nbr[(size_t)k * n + i]);
        }
        run += wb[8];
        __syncthreads();
    }
    // pad: last block of this tap fills [cnt, padded) with sentinels
    if (b == 63) {
        const int cnt = g_meta[64 + kk];
        const int sbase = g_meta[kk] * 128;
        const int padded = (g_meta[kk + 1] - g_meta[kk]) * 128;
        for (int s = cnt + tid; s < padded; s += 256)
            g_pairs[sbase + s] = make_int2(0, -1);
    }
}

// ---------------- center tap: dense GEMM, plain writes ------------------------
#define CEN_SMEM 49152
__global__ __launch_bounds__(256, 2) void center_kernel(
    const uint4* __restrict__ xhi, const uint4* __restrict__ xlo,
    const uint4* __restrict__ wtap, float* __restrict__ out, int n)
{
    extern __shared__ char smem[];
    const uint32_t sb = smem_u32(smem);
    const int tid = threadIdx.x, lane = tid & 31, wid = tid >> 5;
    const int n0 = blockIdx.x * 128;
    const int m0 = (wid & 3) * 32, nb0 = (wid >> 2) * 32;
    const int frow = tid >> 1, fhalf = tid & 1;

    const int g = n0 + frow;
    const uint32_t sz = (g < n) ? 16u : 0u;
    const int gc = min(g, n - 1);
    const char* sh = (const char*)(xhi + (size_t)gc * 8);
    const char* sl = (const char*)(xlo + (size_t)gc * 8);
    #pragma unroll
    for (int j = 0; j < 4; ++j) {
        int c = fhalf * 4 + j;
        uint32_t so = sw128((uint32_t)(frow * 128 + c * 16));
        cpa16(sb + so, sh + c * 16, sz);
        cpa16(sb + 16384 + so, sl + c * 16, sz);
    }
    const char* ws = (const char*)wtap;
    #pragma unroll
    for (int j = 0; j < 2; ++j) {
        int c = tid + j * 256;
        cpa16(sb + 32768 + c * 16, ws + c * 16, 16);
        cpa16(sb + 40960 + c * 16, ws + 8192 + c * 16, 16);
    }
    CP_COMMIT(); CP_WAIT0();
    __syncthreads();

    const uint32_t arow = lane & 15, agrp = (lane >> 4) * 16;
    uint32_t aoff[4][2], boff[4][2];
    #pragma unroll
    for (int kc = 0; kc < 4; ++kc) {
        #pragma unroll
        for (int mi = 0; mi < 2; ++mi)
            aoff[kc][mi] = sw128((uint32_t)((m0 + mi * 16 + arow) * 128 + kc * 32) + agrp);
        #pragma unroll
        for (int ni = 0; ni < 2; ++ni)
            boff[kc][ni] = sw128((uint32_t)((nb0 + ni * 16 + arow) * 128 + kc * 32) + agrp);
    }

    float acc[2][4][4];
    #pragma unroll
    for (int i = 0; i < 2; ++i)
        #pragma unroll
        for (int j = 0; j < 4; ++j)
            #pragma unroll
            for (int q = 0; q < 4; ++q) acc[i][j][q] = 0.f;

    tile_mma(sb, sb + 16384, sb + 32768, sb + 40960, aoff, boff, acc);

    const int rq = lane >> 2, cq = (lane & 3) * 2;
    #pragma unroll
    for (int mi = 0; mi < 2; ++mi)
        #pragma unroll
        for (int nt = 0; nt < 4; ++nt) {
            int col = nb0 + nt * 8 + cq;
            int r0 = n0 + m0 + mi * 16 + rq;
            if (r0 < n)
                *(float2*)(out + (size_t)r0 * CCH + col) = make_float2(acc[mi][nt][0], acc[mi][nt][1]);
            int r1 = r0 + 8;
            if (r1 < n)
                *(float2*)(out + (size_t)r1 * CCH + col) = make_float2(acc[mi][nt][2], acc[mi][nt][3]);
        }
}

// ---------------- scatter conv: compacted tiles + vector RED ------------------
#define SCA(s)     ((s) * 32768)            // hi 16KB + lo 16KB
#define SCW(s)     (65536 + (s) * 16384)    // hi 8KB + lo 8KB
#define SCP(ps)    (98304 + (ps) * 1024)    // pairs, 3 stages
#define SC_TB      101376
#define SC_SMEM    101504

__global__ __launch_bounds__(256, 2) void scatter_kernel(
    const uint4* __restrict__ xhi, const uint4* __restrict__ xlo,
    const uint4* __restrict__ wt, float* __restrict__ out)
{
    extern __shared__ char smem[];
    const uint32_t sb = smem_u32(smem);
    const int tid = threadIdx.x, lane = tid & 31, wid = tid >> 5;
    const int m0 = (wid & 3) * 32, nb0 = (wid >> 2) * 32;
    const int frow = tid >> 1, fhalf = tid & 1;

    int* stb = (int*)(smem + SC_TB);
    if (tid < 27) stb[tid] = g_meta[tid];
    __syncthreads();
    const int ntiles = stb[26];

    int t = blockIdx.x;
    if (t >= ntiles) return;

    // precomputed offsets
    const uint32_t arow = lane & 15, agrp = (lane >> 4) * 16;
    uint32_t aoff[4][2], boff[4][2];
    #pragma unroll
    for (int kc = 0; kc < 4; ++kc) {
        #pragma unroll
        for (int mi = 0; mi < 2; ++mi)
            aoff[kc][mi] = sw128((uint32_t)((m0 + mi * 16 + arow) * 128 + kc * 32) + agrp);
        #pragma unroll
        for (int ni = 0; ni < 2; ++ni)
            boff[kc][ni] = sw128((uint32_t)((nb0 + ni * 16 + arow) * 128 + kc * 32) + agrp);
    }
    uint32_t so4[4];
    #pragma unroll
    for (int j = 0; j < 4; ++j)
        so4[j] = sw128((uint32_t)(frow * 128 + (fhalf * 4 + j) * 16));

    auto tapof = [&](int tt) {
        int kk = 0;
        while (kk < 25 && tt >= stb[kk + 1]) ++kk;
        return kk + (kk >= 13 ? 1 : 0);
    };
    auto issuePairs = [&](int tt, int ps) {
        if (tid < 64)
            cpa16(sb + SCP(ps) + tid * 16,
                  (const char*)(g_pairs + (size_t)tt * 128) + tid * 16, 16);
    };
    auto issueA = [&](int s, int ps) {
        const int2* prs = (const int2*)(smem + SCP(ps));
        int in = prs[frow].y;
        uint32_t sz = (in >= 0) ? 16u : 0u;
        int ic = (in >= 0) ? in : 0;
        const char* sh = (const char*)(xhi + (size_t)ic * 8);
        const char* sl = (const char*)(xlo + (size_t)ic * 8);
        #pragma unroll
        for (int j = 0; j < 4; ++j) {
            int c = fhalf * 4 + j;
            cpa16(sb + SCA(s) + so4[j], sh + c * 16, sz);
            cpa16(sb + SCA(s) + 16384 + so4[j], sl + c * 16, sz);
        }
    };
    auto issueW = [&](int s, int k) {
        const char* ws = (const char*)(wt + (size_t)k * 1024);
        #pragma unroll
        for (int j = 0; j < 2; ++j) {
            int c = tid + j * 256;
            cpa16(sb + SCW(s) + c * 16, ws + c * 16, 16);
            cpa16(sb + SCW(s) + 8192 + c * 16, ws + 8192 + c * 16, 16);
        }
    };

    // prologue: pairs(t0), pairs(t1); then A/W(t0)
    issuePairs(t, 0);
    int t1 = t + SCGRID;
    if (t1 < ntiles) issuePairs(t1, 1);
    CP_COMMIT(); CP_WAIT0();
    __syncthreads();
    issueA(0, 0);
    issueW(0, tapof(t));
    CP_COMMIT();

    const int rq = lane >> 2;
    const int cb = (lane & 2) * 2;       // 0 or 4: v4 column base within 8-col tile
    const bool evn = !(lane & 1);
    int i = 0;
    while (true) {
        const int s = i & 1;
        const int ps = i % 3;
        CP_WAIT0();
        __syncthreads();

        int tn = t + SCGRID;
        bool hn = (tn < ntiles);
        if (hn) {
            issueA(s ^ 1, (i + 1) % 3);
            issueW(s ^ 1, tapof(tn));
            int tn2 = tn + SCGRID;
            if (tn2 < ntiles) issuePairs(tn2, (i + 2) % 3);
            CP_COMMIT();
        }

        float acc[2][4][4];
        #pragma unroll
        for (int a = 0; a < 2; ++a)
            #pragma unroll
            for (int b = 0; b < 4; ++b)
                #pragma unroll
                for (int q = 0; q < 4; ++q) acc[a][b][q] = 0.f;

        tile_mma(sb + SCA(s), sb + SCA(s) + 16384, sb + SCW(s), sb + SCW(s) + 8192,
                 aoff, boff, acc);

        // epilogue: butterfly lanes (l, l^1) to form 16B vectors, one v4 RED each
        const int2* prs = (const int2*)(smem + SCP(ps));
        #pragma unroll
        for (int mi = 0; mi < 2; ++mi) {
            int r = m0 + mi * 16 + rq;
            int2 p0 = prs[r];         // row r (lanes l and l^1 agree)
            int2 p1 = prs[r + 8];     // row r+8
            float* o0 = out + (size_t)p0.x * CCH;
            float* o1 = out + (size_t)p1.x * CCH;
            #pragma unroll
            for (int nt = 0; nt < 4; ++nt) {
                float a0 = acc[mi][nt][0], a1 = acc[mi][nt][1];
                float a2 = acc[mi][nt][2], a3 = acc[mi][nt][3];
                float b0 = __shfl_xor_sync(0xffffffffu, a0, 1);
                float b1 = __shfl_xor_sync(0xffffffffu, a1, 1);
                float b2 = __shfl_xor_sync(0xffffffffu, a2, 1);
                float b3 = __shfl_xor_sync(0xffffffffu, a3, 1);
                int col = nb0 + nt * 8 + cb;
                if (evn) {
                    if (p0.y >= 0) redadd4(o0 + col, a0, a1, b0, b1);
                } else {
                    if (p1.y >= 0) redadd4(o1 + col, b2, b3, a2, a3);
                }
            }
        }
        if (!hn) break;
        t = tn;
        ++i;
    }
}

// ---------------- bnrelu: BN + ReLU fused, writes bf16 hi/lo -------------------
__global__ __launch_bounds__(256) void bnrelu_kernel(const float* __restrict__ x, int nchunk)
{
    int i = blockIdx.x * blockDim.x + threadIdx.x;
    if (i >= nchunk) return;
    const float4* x4 = (const float4*)x;
    float4 a = x4[2 * i], b = x4[2 * i + 1];
    int c = (i * 8) & 63;
    a.x = fmaxf(a.x * g_stats[c + 0] + g_stats[64 + c + 0], 0.f);
    a.y = fmaxf(a.y * g_stats[c + 1] + g_stats[64 + c + 1], 0.f);
    a.z = fmaxf(a.z * g_stats[c + 2] + g_stats[64 + c + 2], 0.f);
    a.w = fmaxf(a.w * g_stats[c + 3] + g_stats[64 + c + 3], 0.f);
    b.x = fmaxf(b.x * g_stats[c + 4] + g_stats[64 + c + 4], 0.f);
    b.y = fmaxf(b.y * g_stats[c + 5] + g_stats[64 + c + 5], 0.f);
    b.z = fmaxf(b.z * g_stats[c + 6] + g_stats[64 + c + 6], 0.f);
    b.w = fmaxf(b.w * g_stats[c + 7] + g_stats[64 + c + 7], 0.f);
    uint4 h, l;
    split8(a, b, h, l);
    g_xhi[i] = h; g_xlo[i] = l;
}

// ---------------- BN stats (deterministic) ------------------------------------
__global__ __launch_bounds__(256) void stats_kernel(const float* __restrict__ buf, int n)
{
    __shared__ float s[4][128];
    const int tid = threadIdx.x, lane = tid & 63, grp = tid >> 6;
    const int chunk = (n + SBLK - 1) / SBLK;
    const int r0 = blockIdx.x * chunk;
    const int r1 = min(r0 + chunk, n);
    float sm = 0.f, sq = 0.f;
    for (int r = r0 + grp; r < r1; r += 4) {
        float v = buf[(size_t)r * CCH + lane];
        sm += v; sq += v * v;
    }
    s[grp][lane] = sm; s[grp][64 + lane] = sq;
    __syncthreads();
    if (tid < 128)
        g_part[(size_t)blockIdx.x * 128 + tid] = s[0][tid] + s[1][tid] + s[2][tid] + s[3][tid];
}

__global__ __launch_bounds__(512) void reduce_kernel(
    const float* __restrict__ gamma, const float* __restrict__ beta, int n)
{
    __shared__ float s[4][128];
    const int tid = threadIdx.x, col = tid & 127, grp = tid >> 7;
    float acc = 0.f;
    for (int b = grp; b < SBLK; b += 4) acc += g_part[(size_t)b * 128 + col];
    s[grp][col] = acc;
    __syncthreads();
    if (tid < 128) s[0][tid] = s[0][tid] + s[1][tid] + s[2][tid] + s[3][tid];
    __syncthreads();
    if (tid < 64) {
        float inv_n = 1.0f / (float)n;
        float mean = s[0][tid] * inv_n;
        float var = s[0][64 + tid] * inv_n - mean * mean;
        float scale = gamma[tid] * rsqrtf(var + 1e-5f);
        g_stats[tid] = scale;
        g_stats[64 + tid] = beta[tid] - mean * scale;
    }
}

// ---------------- final: BN2 + residual + ReLU --------------------------------
__global__ __launch_bounds__(256) void final_kernel(
    const float* __restrict__ x, const float* __restrict__ feat,
    float* __restrict__ y, int total4)
{
    int i = blockIdx.x * blockDim.x + threadIdx.x;
    if (i >= total4) return;
    float4 v = reinterpret_cast<const float4*>(x)[i];
    float4 f = reinterpret_cast<const float4*>(feat)[i];
    int c = (i * 4) & 63;
    float4 o;
    o.x = fmaxf(v.x * g_stats[c + 0] + g_stats[64 + c + 0] + f.x, 0.f);
    o.y = fmaxf(v.y * g_stats[c + 1] + g_stats[64 + c + 1] + f.y, 0.f);
    o.z = fmaxf(v.z * g_stats[c + 2] + g_stats[64 + c + 2] + f.z, 0.f);
    o.w = fmaxf(v.w * g_stats[c + 3] + g_stats[64 + c + 3] + f.w, 0.f);
    reinterpret_cast<float4*>(y)[i] = o;
}

// ---------------- launch ------------------------------------------------------
extern "C" void kernel_launch(void* const* d_in, const int* in_sizes, int n_in,
                              void* d_out, int out_size)
{
    const float* feat   = (const float*)d_in[0];
    const int*   nbr    = (const int*)  d_in[1];
    const float* valid  = (const float*)d_in[2];
    const float* W1     = (const float*)d_in[3];
    const float* gamma1 = (const float*)d_in[4];
    const float* beta1  = (const float*)d_in[5];
    const float* W2     = (const float*)d_in[6];
    const float* gamma2 = (const float*)d_in[7];
    const float* beta2  = (const float*)d_in[8];
    float* out = (float*)d_out;

    const int n = in_sizes[0] / CCH;
    const int nchunk = n * 8;
    const int total4 = (n * CCH) / 4;

    float *buf1; uint4 *xhi, *xlo, *wt1, *wt2;
    cudaGetSymbolAddress((void**)&buf1, g_buf1);
    cudaGetSymbolAddress((void**)&xhi, g_xhi);
    cudaGetSymbolAddress((void**)&xlo, g_xlo);
    cudaGetSymbolAddress((void**)&wt1, g_wt1);
    cudaGetSymbolAddress((void**)&wt2, g_wt2);

    cudaFuncSetAttribute(center_kernel, cudaFuncAttributeMaxDynamicSharedMemorySize, CEN_SMEM);
    cudaFuncSetAttribute(scatter_kernel, cudaFuncAttributeMaxDynamicSharedMemorySize, SC_SMEM);

    dim3 cenGrid((n + 127) / 128);
    dim3 prepGrid(54 + (nchunk + 255) / 256);
    dim3 ewGrid((total4 + 255) / 256);
    dim3 bnGrid((nchunk + 255) / 256);

    // launch order chosen so the ncu window (-s 5 -c 1) lands on scatter_kernel
    prep_kernel<<<prepGrid, 256>>>(W1, W2, feat, nchunk);            // 0
    count_kernel<<<26 * 64, 256>>>(valid, n);                        // 1
    scan_kernel<<<1, 1024>>>();                                      // 2
    fill_kernel<<<26 * 64, 256>>>(nbr, valid, n);                    // 3 (pads too)

    // conv1
    center_kernel<<<cenGrid, 256, CEN_SMEM>>>(xhi, xlo, wt1 + 13 * 1024, buf1, n);  // 4
    scatter_kernel<<<SCGRID, 256, SC_SMEM>>>(xhi, xlo, wt1, buf1);                  // 5 <- profiled
    stats_kernel<<<SBLK, 256>>>(buf1, n);                            // 6
    reduce_kernel<<<1, 512>>>(gamma1, beta1, n);                     // 7
    bnrelu_kernel<<<bnGrid, 256>>>(buf1, nchunk);                    // 8

    // conv2
    center_kernel<<<cenGrid, 256, CEN_SMEM>>>(xhi, xlo, wt2 + 13 * 1024, buf1, n);  // 9
    scatter_kernel<<<SCGRID, 256, SC_SMEM>>>(xhi, xlo, wt2, buf1);                  // 10
    stats_kernel<<<SBLK, 256>>>(buf1, n);                            // 11
    reduce_kernel<<<1, 512>>>(gamma2, beta2, n);                     // 12
    final_kernel<<<ewGrid, 256>>>(buf1, feat, out, total4);          // 13
}